// round 6
// baseline (speedup 1.0000x reference)
#include <cuda_runtime.h>

#define NB 512
#define NS 16384
#define NFFT 16384
#define HFFT 8192
#define NT 1024
#define SBUF_N 16384
// Bank-spreading bijection: XOR low nibble with (j2&3 | (s3&3)<<2) from bits 4-5 and 12-13.
#define G(k) ((k) ^ ((((k) >> 4) & 3) | ((((k) >> 12) & 3) << 2)))

// Global accumulators: 0=pearson(1-r) sum, 1=cos sum, 2=nmi sum, 3=|xp-tp| sum, 4=tp sum
__device__ double g_acc[5];
__device__ unsigned g_cnt;

struct Scr {
    double red[5][32];
    float  fmm[4][32];
    float  hxy[20];
    int    hist[100];
    float  amaxv[32];
    int    amaxi[32];
    float  bc[4];
    int    last;
};

// ---------------- small helpers ----------------
__device__ __forceinline__ float2 cmul(float2 a, float2 b) {
    return make_float2(a.x * b.x - a.y * b.y, a.x * b.y + a.y * b.x);
}

__device__ __forceinline__ int BR4(int x) {
    return ((x & 1) << 3) | ((x & 2) << 1) | ((x & 4) >> 1) | ((x & 8) >> 3);
}

// twiddle constants exp(-i*pi*e/16); switch form folds to immediates under full unroll
__device__ __forceinline__ float twc(int e) {
    switch (e & 15) {
        case 0:  return  1.0f;
        case 1:  return  0.980785280403f;
        case 2:  return  0.923879532511f;
        case 3:  return  0.831469612303f;
        case 4:  return  0.707106781187f;
        case 5:  return  0.555570233020f;
        case 6:  return  0.382683432365f;
        case 7:  return  0.195090322016f;
        case 8:  return  0.0f;
        case 9:  return -0.195090322016f;
        case 10: return -0.382683432365f;
        case 11: return -0.555570233020f;
        case 12: return -0.707106781187f;
        case 13: return -0.831469612303f;
        case 14: return -0.923879532511f;
        default: return -0.980785280403f;
    }
}
__device__ __forceinline__ float tws(int e) {
    switch (e & 15) {
        case 0:  return  0.0f;
        case 1:  return -0.195090322016f;
        case 2:  return -0.382683432365f;
        case 3:  return -0.555570233020f;
        case 4:  return -0.707106781187f;
        case 5:  return -0.831469612303f;
        case 6:  return -0.923879532511f;
        case 7:  return -0.980785280403f;
        case 8:  return -1.0f;
        case 9:  return -0.980785280403f;
        case 10: return -0.923879532511f;
        case 11: return -0.831469612303f;
        case 12: return -0.707106781187f;
        case 13: return -0.555570233020f;
        case 14: return -0.382683432365f;
        default: return -0.195090322016f;
    }
}

__device__ __forceinline__ void bfly(float2& p, float2& q, int e) {
    float c = twc(e), s = tws(e);
    float ax = p.x, ay = p.y, bx = q.x, by = q.y;
    p.x = ax + bx; p.y = ay + by;
    float dx = ax - bx, dy = ay - by;
    q.x = dx * c - dy * s;
    q.y = dx * s + dy * c;
}

// DIF radix-2 FFT of 16 points. Output position q holds frequency brev4(q).
__device__ __forceinline__ void fft16(float2* v) {
#pragma unroll
    for (int h = 8; h >= 1; h >>= 1) {
#pragma unroll
        for (int g = 0; g < 16; g += 2 * h) {
#pragma unroll
            for (int j = 0; j < h; j++) {
                bfly(v[g + j], v[g + j + h], j * (16 / h));
            }
        }
    }
}

// ---- 16384-pt FFT, 1024 threads, 16 pts/thread: 16 x 16 x 16 x (shuffle-4) ----
// Entry: v[r] = input[tid + 1024*r] (natural order).
// SCATTER=true : spectrum written to sbuf[G(k)] in natural frequency order.
// SCATTER=false: per-thread argmax of Re(X[k]) -> (*bvp, *bip), min-index ties.
template <bool SCATTER>
__device__ __forceinline__ void fft16k(float2 (&v)[16], float2* __restrict__ sbuf, int tid,
                                       float* bvp, int* bip)
{
    __syncthreads();   // prior sbuf readers done before pass-1 stores

    // ---- pass 1: DFT_16 over stride-1024, twiddle W_N^{t*j}, store [j][t] ----
    fft16(v);
    {
        float sp, cp;
        sincospif((float)tid * (1.0f / 8192.0f), &sp, &cp);
        float2 step = make_float2(cp, -sp);
        float2 w = make_float2(1.0f, 0.0f);
#pragma unroll
        for (int j = 0; j < 16; j++) {
            sbuf[j * 1024 + tid] = cmul(v[BR4(j)], w);
            w = cmul(w, step);
        }
    }
    __syncthreads();

    // ---- pass 2: within each 1024-row, DFT_16 over stride-64, twiddle W_1024^{m*j2} ----
    {
        int j = tid >> 6, m = tid & 63;
        int base = j * 1024 + m;
#pragma unroll
        for (int r2 = 0; r2 < 16; r2++) v[r2] = sbuf[base + 64 * r2];
        __syncthreads();
        fft16(v);
        float sp, cp;
        sincospif((float)m * (1.0f / 512.0f), &sp, &cp);
        float2 step = make_float2(cp, -sp);
        float2 w = make_float2(1.0f, 0.0f);
        int rowb = j * 1024;
#pragma unroll
        for (int j2 = 0; j2 < 16; j2++) {
            sbuf[rowb + j2 * 64 + (m ^ (4 * (j2 & 7)))] = cmul(v[BR4(j2)], w);
            w = cmul(w, step);
        }
    }
    __syncthreads();

    // ---- pass 3: 64-pt segments (j,j2): DFT_16 over r3 + twiddle + shuffle-DFT_4 ----
    int seg = tid >> 2, m3 = tid & 3;
    int j2s = seg & 15;
    {
        int base = seg * 64;
        int x4 = 4 * (j2s & 7);
#pragma unroll
        for (int r3 = 0; r3 < 16; r3++) v[r3] = sbuf[base + ((m3 + 4 * r3) ^ x4)];
    }
    fft16(v);
    {   // twiddle W_64^{j3*m3}
        float sp, cp;
        sincospif((float)m3 * (1.0f / 32.0f), &sp, &cp);
        float2 step = make_float2(cp, -sp);
        float2 w = make_float2(1.0f, 0.0f);
#pragma unroll
        for (int j3 = 0; j3 < 16; j3++) {
            v[BR4(j3)] = cmul(v[BR4(j3)], w);
            w = cmul(w, step);
        }
    }
    // shuffle DFT_4 over m3 (lanes l, l^1, l^2, l^3 own one segment)
    {
        bool hi = (m3 & 2) != 0, od = (m3 & 1) != 0;
#pragma unroll
        for (int q = 0; q < 16; q++) {
            float2 u = v[q];
            float px = __shfl_xor_sync(0xffffffffu, u.x, 2);
            float py = __shfl_xor_sync(0xffffffffu, u.y, 2);
            float t1x = hi ? (px - u.x) : (u.x + px);   // E (low) / O (high)
            float t1y = hi ? (py - u.y) : (u.y + py);
            float qx = __shfl_xor_sync(0xffffffffu, t1x, 1);
            float qy = __shfl_xor_sync(0xffffffffu, t1y, 1);
            // m3=0: t+q | m3=1: q-t | m3=2: t - i*q | m3=3: q + i*t
            float tx = od ? (hi ? -t1y : -t1x) : t1x;
            float ty = od ? (hi ?  t1x : -t1y) : t1y;
            float qx2 = hi ? (od ? qx :  qy) : qx;
            float qy2 = hi ? (od ? qy : -qx) : qy;
            v[q] = make_float2(tx + qx2, ty + qy2);
        }
    }
    int s3 = (m3 == 1) ? 2 : ((m3 == 2) ? 1 : m3);       // brev2 of m3
    int kbase = (seg >> 4) + 16 * j2s + 4096 * s3;       // k = j + 16*j2 + 256*j3 + 4096*s3

    if (SCATTER) {
        __syncthreads();   // all pass-3 loads done before overwriting via G()
#pragma unroll
        for (int j3 = 0; j3 < 16; j3++) {
            sbuf[G(kbase + 256 * j3)] = v[BR4(j3)];
        }
        __syncthreads();
    } else {
        float bv = -3.4e38f; int bi = 0;
#pragma unroll
        for (int j3 = 0; j3 < 16; j3++) {
            int k = kbase + 256 * j3;
            float re = v[BR4(j3)].x;
            if (re > bv || (re == bv && k < bi)) { bv = re; bi = k; }
        }
        *bvp = bv; *bip = bi;
    }
}

// Hermitian unpack at arbitrary frequency j (mod N): returns (Xr, Xi, Tr, Ti)
__device__ __forceinline__ float4 unp(const float2* __restrict__ sbuf, int j) {
    int a = G(j & (NFFT - 1));
    int c = G((NFFT - j) & (NFFT - 1));
    float2 Z1 = sbuf[a], Z2 = sbuf[c];
    return make_float4(0.5f * (Z1.x + Z2.x),  0.5f * (Z1.y - Z2.y),
                       0.5f * (Z1.y + Z2.y), -0.5f * (Z1.x - Z2.x));
}

// Stencil + phase-only correlation at frequency k. pa/pt accumulate power-spectrum terms.
__device__ __forceinline__ float2 phase_corr(const float2* __restrict__ sbuf, int k,
                                             double& pa, double& pt) {
    float4 U  = unp(sbuf, k);
    float xp = U.x * U.x + U.y * U.y;
    float tp = U.z * U.z + U.w * U.w;
    pa += (double)fabsf(xp - tp);
    pt += (double)tp;

    float4 Um = unp(sbuf, k - 1);
    float4 Up = unp(sbuf, k + 1);
    float Xwr = 0.5f * U.x - 0.25f * (Um.x + Up.x);
    float Xwi = 0.5f * U.y - 0.25f * (Um.y + Up.y);
    float Twr = 0.5f * U.z - 0.25f * (Um.z + Up.z);
    float Twi = 0.5f * U.w - 0.25f * (Um.w + Up.w);
    float Cr = Xwr * Twr + Xwi * Twi;   // Xw * conj(Tw)
    float Ci = Xwi * Twr - Xwr * Twi;
    float inv = rsqrtf(Cr * Cr + Ci * Ci);
    return make_float2(Cr * inv, Ci * inv);
}

// ---------------- main per-row kernel ----------------
__global__ void __launch_bounds__(NT, 1)
row_kernel(const float* __restrict__ pred, const float* __restrict__ targ,
           const int* __restrict__ ip, const int* __restrict__ ep,
           float* __restrict__ out)
{
    extern __shared__ char smem[];
    float2* sbuf = (float2*)smem;
    Scr* scr = (Scr*)(smem + (size_t)SBUF_N * sizeof(float2));

    const int tid  = threadIdx.x;
    const int lane = tid & 31;
    const int wid  = tid >> 5;
    const int b    = blockIdx.x;
    const int ii   = *ip;
    const float* x = pred + (size_t)ii * NB * NS + (size_t)b * NS;
    const float* y = targ + (size_t)b * NS;

    // ---- single global read of the row; feeds stats, MI, and FFT input ----
    float2 v[16];
#pragma unroll
    for (int r = 0; r < 16; r++) {
        int n = tid + NT * r;
        v[r] = make_float2(x[n], y[n]);
    }

    // ================= Phase 1: Pearson stats + min/max =================
    double sx = 0, sy = 0, sxy = 0, sxx = 0, syy = 0;
    float xmn = 3.4e38f, xmx = -3.4e38f, ymn = 3.4e38f, ymx = -3.4e38f;
#pragma unroll
    for (int r = 0; r < 16; r++) {
        float xv = v[r].x, yv = v[r].y;
        sx += xv; sy += yv;
        sxy += (double)xv * yv;
        sxx += (double)xv * xv;
        syy += (double)yv * yv;
        xmn = fminf(xmn, xv); xmx = fmaxf(xmx, xv);
        ymn = fminf(ymn, yv); ymx = fmaxf(ymx, yv);
    }
#pragma unroll
    for (int o = 16; o; o >>= 1) {
        sx  += __shfl_down_sync(0xffffffffu, sx,  o);
        sy  += __shfl_down_sync(0xffffffffu, sy,  o);
        sxy += __shfl_down_sync(0xffffffffu, sxy, o);
        sxx += __shfl_down_sync(0xffffffffu, sxx, o);
        syy += __shfl_down_sync(0xffffffffu, syy, o);
        xmn = fminf(xmn, __shfl_down_sync(0xffffffffu, xmn, o));
        xmx = fmaxf(xmx, __shfl_down_sync(0xffffffffu, xmx, o));
        ymn = fminf(ymn, __shfl_down_sync(0xffffffffu, ymn, o));
        ymx = fmaxf(ymx, __shfl_down_sync(0xffffffffu, ymx, o));
    }
    if (lane == 0) {
        scr->red[0][wid] = sx;  scr->red[1][wid] = sy;  scr->red[2][wid] = sxy;
        scr->red[3][wid] = sxx; scr->red[4][wid] = syy;
        scr->fmm[0][wid] = xmn; scr->fmm[1][wid] = xmx;
        scr->fmm[2][wid] = ymn; scr->fmm[3][wid] = ymx;
    }
    if (tid < 100) scr->hist[tid] = 0;   // zero MI histogram concurrently
    __syncthreads();
    if (tid < 32) {
        double r0 = scr->red[0][lane];
        double r1 = scr->red[1][lane];
        double r2 = scr->red[2][lane];
        double r3 = scr->red[3][lane];
        double r4 = scr->red[4][lane];
        float m0 = scr->fmm[0][lane];
        float m1 = scr->fmm[1][lane];
        float m2 = scr->fmm[2][lane];
        float m3v = scr->fmm[3][lane];
#pragma unroll
        for (int o = 16; o; o >>= 1) {
            r0 += __shfl_down_sync(0xffffffffu, r0, o);
            r1 += __shfl_down_sync(0xffffffffu, r1, o);
            r2 += __shfl_down_sync(0xffffffffu, r2, o);
            r3 += __shfl_down_sync(0xffffffffu, r3, o);
            r4 += __shfl_down_sync(0xffffffffu, r4, o);
            m0 = fminf(m0, __shfl_down_sync(0xffffffffu, m0, o));
            m1 = fmaxf(m1, __shfl_down_sync(0xffffffffu, m1, o));
            m2 = fminf(m2, __shfl_down_sync(0xffffffffu, m2, o));
            m3v = fmaxf(m3v, __shfl_down_sync(0xffffffffu, m3v, o));
        }
        if (lane == 0) {
            const double N = (double)NS;
            double num = N * r2 - r0 * r1;
            double den = sqrt((N * r3 - r0 * r0) * (N * r4 - r1 * r1));
            atomicAdd(&g_acc[0], 1.0 - num / den);
            scr->bc[0] = m0; scr->bc[1] = m1; scr->bc[2] = m2; scr->bc[3] = m3v;
        }
    }
    __syncthreads();
    xmn = scr->bc[0]; xmx = scr->bc[1]; ymn = scr->bc[2]; ymx = scr->bc[3];

    // ================= Phase 2: mutual information =================
    {
        float bwx = __fdiv_rn(xmx - xmn, 10.0f);
        float bwy = __fdiv_rn(ymx - ymn, 10.0f);
#pragma unroll
        for (int r = 0; r < 16; r++) {
            int ix = (int)__fdiv_rn(v[r].x - xmn, bwx);
            int iy = (int)__fdiv_rn(v[r].y - ymn, bwy);
            ix = min(max(ix, 0), 9);
            iy = min(max(iy, 0), 9);
            atomicAdd(&scr->hist[ix * 10 + iy], 1);
        }
    }
    __syncthreads();
    if (tid < 32) {
        const float denom = 8388608.0f;  // B*S — faithful to reference normalization
        float rs = 0.f;
        if (lane < 10) {
#pragma unroll
            for (int c = 0; c < 10; c++) rs += (float)scr->hist[lane * 10 + c];
            scr->hxy[lane] = rs;
        } else if (lane < 20) {
            int c = lane - 10;
#pragma unroll
            for (int a = 0; a < 10; a++) rs += (float)scr->hist[a * 10 + c];
            scr->hxy[lane] = rs;
        }
        __syncwarp();
        float mi = 0.f;
#pragma unroll
        for (int u = 0; u < 4; u++) {
            int l = lane + 32 * u;
            if (l < 100) {
                int a2 = l / 10, c2 = l - 10 * a2;
                float px  = scr->hxy[a2] / denom;
                float py  = scr->hxy[10 + c2] / denom;
                float pxy = (float)scr->hist[l] / denom;
                mi += pxy * logf((pxy + 1e-8f) / (px * py + 1e-8f));
            }
        }
        float he = 0.f;
        if (lane < 20) {
            float p = scr->hxy[lane] / denom;
            he = -p * logf(p + 1e-8f);
        }
#pragma unroll
        for (int o = 16; o; o >>= 1) {
            mi += __shfl_down_sync(0xffffffffu, mi, o);
            he += __shfl_down_sync(0xffffffffu, he, o);
        }
        if (lane == 0) atomicAdd(&g_acc[2], (double)(mi / (he * 0.5f)));
    }

    // ================= Phase 3: single unwindowed FFT Z = FFT(x + i*y) =================
    float bv; int bi;
    fft16k<true>(v, sbuf, tid, &bv, &bi);   // natural-order spectrum in sbuf (G-mapped)

    // ---- Phase A (reads only, constant register indices): power spectrum +
    //      frequency-domain Hann (Xw[k] = 0.5 X[k] - 0.25(X[k-1]+X[k+1]), exact) + phase-only C
    double pa = 0.0, pt = 0.0;
#pragma unroll
    for (int r = 0; r < 8; r++) {
        v[r] = phase_corr(sbuf, tid + NT * r, pa, pt);
    }
    float2 c81 = make_float2(0.f, 0.f);
    if (tid == 0) c81 = phase_corr(sbuf, HFFT, pa, pt);   // k = 8192 (self-conjugate, Ci = 0 exactly)
    __syncthreads();

    // ---- Phase B (writes): store D = conj(C) with Hermitian extension, in place.
#pragma unroll
    for (int r = 0; r < 8; r++) {
        int k = tid + NT * r;
        float2 C = v[r];
        sbuf[G(k)]                       = make_float2(C.x, -C.y);  // conj(C[k])
        sbuf[G((NFFT - k) & (NFFT - 1))] = make_float2(C.x,  C.y);  // C[k] at N-k
    }
    if (tid == 0) sbuf[G(HFFT)] = make_float2(c81.x, -c81.y);

    // power-spectrum reduction (its barrier also orders Phase B writes before fft#2 loads)
#pragma unroll
    for (int o = 16; o; o >>= 1) {
        pa += __shfl_down_sync(0xffffffffu, pa, o);
        pt += __shfl_down_sync(0xffffffffu, pt, o);
    }
    if (lane == 0) { scr->red[0][wid] = pa; scr->red[1][wid] = pt; }
    __syncthreads();
    if (tid < 32) {
        double p0 = scr->red[0][lane];
        double p1 = scr->red[1][lane];
#pragma unroll
        for (int o = 16; o; o >>= 1) {
            p0 += __shfl_down_sync(0xffffffffu, p0, o);
            p1 += __shfl_down_sync(0xffffffffu, p1, o);
        }
        if (lane == 0) {
            atomicAdd(&g_acc[3], p0);
            atomicAdd(&g_acc[4], p1);
        }
    }

    // ================= Phase 4: inverse FFT via forward FFT of conj, argmax =================
#pragma unroll
    for (int r = 0; r < 16; r++) v[r] = sbuf[G(tid + NT * r)];
    fft16k<false>(v, sbuf, tid, &bv, &bi);

    for (int o = 16; o; o >>= 1) {
        float ov = __shfl_down_sync(0xffffffffu, bv, o);
        int   oi = __shfl_down_sync(0xffffffffu, bi, o);
        if (ov > bv || (ov == bv && oi < bi)) { bv = ov; bi = oi; }
    }
    if (lane == 0) { scr->amaxv[wid] = bv; scr->amaxi[wid] = bi; }
    __syncthreads();
    if (tid < 32) {
        float ov = scr->amaxv[lane];
        int   oi = scr->amaxi[lane];
#pragma unroll
        for (int o = 16; o; o >>= 1) {
            float pv = __shfl_down_sync(0xffffffffu, ov, o);
            int   pi = __shfl_down_sync(0xffffffffu, oi, o);
            if (pv > ov || (pv == ov && pi < oi)) { ov = pv; oi = pi; }
        }
        if (lane == 0)
            atomicAdd(&g_acc[1], (double)cospif((float)oi * (1.0f / 8192.0f)));
    }

    // ================= Finalize: last block computes the loss and resets state =================
    if (tid == 0) {
        __threadfence();
        unsigned t = atomicAdd(&g_cnt, 1u);
        scr->last = (t == (unsigned)(NB - 1));
    }
    __syncthreads();
    if (scr->last && tid == 0) {
        __threadfence();
        double a0 = atomicAdd(&g_acc[0], 0.0);
        double a1 = atomicAdd(&g_acc[1], 0.0);
        double a2 = atomicAdd(&g_acc[2], 0.0);
        double a3 = atomicAdd(&g_acc[3], 0.0);
        double a4 = atomicAdd(&g_acc[4], 0.0);
        int e = *ep;
        double loss = a0 / (double)NB;
        if (e >= 400) {
            loss += 1.0 - a1 / (double)NB;   // phase correlation term
            loss += a3 / a4;                 // power spectrum (means over same count cancel)
        }
        if (e >= 700) {
            loss += 1.0 - a2 / (double)NB;   // mutual information term
        }
        out[0] = (float)loss;
        // reset accumulators for the next (graph-replayed) launch
        g_acc[0] = 0.0; g_acc[1] = 0.0; g_acc[2] = 0.0; g_acc[3] = 0.0; g_acc[4] = 0.0;
        __threadfence();
        g_cnt = 0u;
    }
}

extern "C" void kernel_launch(void* const* d_in, const int* in_sizes, int n_in,
                              void* d_out, int out_size) {
    const float* pred = (const float*)d_in[0];
    const float* targ = (const float*)d_in[1];
    const int*   ip   = (const int*)d_in[2];
    const int*   ep   = (const int*)d_in[3];
    float* out = (float*)d_out;

    size_t smem = (size_t)SBUF_N * sizeof(float2) + sizeof(Scr);
    cudaFuncSetAttribute(row_kernel, cudaFuncAttributeMaxDynamicSharedMemorySize, (int)smem);

    row_kernel<<<NB, NT, smem>>>(pred, targ, ip, ep, out);
}

// round 11
// speedup vs baseline: 1.5230x; 1.5230x over previous
#include <cuda_runtime.h>

#define NB 512
#define NS 16384
#define NFFT 16384
#define HFFT 8192
#define NT 512
#define SBUF_N 16896
#define SKEW(k) ((k) + ((k) >> 5))
#define CB2 8448   // FFT#2 staging base (slots 8448..16639; C lives in 0..8192)

// Global accumulators: 0=pearson(1-r) sum, 1=cos sum, 2=nmi sum, 3=|xp-tp| sum, 4=tp sum
__device__ double g_acc[5];
__device__ unsigned g_cnt;

struct Scr {
    double red[5][16];
    float  fmm[4][16];
    float  hxy[20];
    int    hist[100];
    float  amaxv[16];
    int    amaxi[16];
    float  bc[4];
    int    last;
};

// ---------------- small helpers ----------------
__device__ __forceinline__ float2 cmul(float2 a, float2 b) {
    return make_float2(a.x * b.x - a.y * b.y, a.x * b.y + a.y * b.x);
}

__device__ __forceinline__ int BR5(int x) {
    return ((x & 1) << 4) | ((x & 2) << 2) | (x & 4) | ((x & 8) >> 2) | ((x & 16) >> 4);
}
__device__ __forceinline__ int BR4(int x) {
    return ((x & 1) << 3) | ((x & 2) << 1) | ((x & 4) >> 1) | ((x & 8) >> 3);
}

// twiddle constants exp(-i*pi*e/16); switch form folds to immediates under full unroll
__device__ __forceinline__ float twc(int e) {
    switch (e & 15) {
        case 0:  return  1.0f;
        case 1:  return  0.980785280403f;
        case 2:  return  0.923879532511f;
        case 3:  return  0.831469612303f;
        case 4:  return  0.707106781187f;
        case 5:  return  0.555570233020f;
        case 6:  return  0.382683432365f;
        case 7:  return  0.195090322016f;
        case 8:  return  0.0f;
        case 9:  return -0.195090322016f;
        case 10: return -0.382683432365f;
        case 11: return -0.555570233020f;
        case 12: return -0.707106781187f;
        case 13: return -0.831469612303f;
        case 14: return -0.923879532511f;
        default: return -0.980785280403f;
    }
}
__device__ __forceinline__ float tws(int e) {
    switch (e & 15) {
        case 0:  return  0.0f;
        case 1:  return -0.195090322016f;
        case 2:  return -0.382683432365f;
        case 3:  return -0.555570233020f;
        case 4:  return -0.707106781187f;
        case 5:  return -0.831469612303f;
        case 6:  return -0.923879532511f;
        case 7:  return -0.980785280403f;
        case 8:  return -1.0f;
        case 9:  return -0.980785280403f;
        case 10: return -0.923879532511f;
        case 11: return -0.831469612303f;
        case 12: return -0.707106781187f;
        case 13: return -0.555570233020f;
        case 14: return -0.382683432365f;
        default: return -0.195090322016f;
    }
}

__device__ __forceinline__ void bfly(float2& p, float2& q, int e) {
    float c = twc(e), s = tws(e);
    float ax = p.x, ay = p.y, bx = q.x, by = q.y;
    p.x = ax + bx; p.y = ay + by;
    float dx = ax - bx, dy = ay - by;
    q.x = dx * c - dy * s;
    q.y = dx * s + dy * c;
}

// DIF radix-2 FFT of 32 register points. Output position q holds frequency brev5(q).
__device__ __forceinline__ void fft32(float2* v) {
#pragma unroll
    for (int h = 16; h >= 1; h >>= 1) {
#pragma unroll
        for (int g = 0; g < 32; g += 2 * h) {
#pragma unroll
            for (int j = 0; j < h; j++) {
                bfly(v[g + j], v[g + j + h], j * (16 / h));
            }
        }
    }
}

// DIF radix-2 FFT of 16 points. Output position q holds frequency brev4(q).
__device__ __forceinline__ void fft16(float2* v) {
#pragma unroll
    for (int h = 8; h >= 1; h >>= 1) {
#pragma unroll
        for (int g = 0; g < 16; g += 2 * h) {
#pragma unroll
            for (int j = 0; j < h; j++) {
                bfly(v[g + j], v[g + j + h], j * (16 / h));
            }
        }
    }
}

// ---- FFT#1: 16384-pt, 512 threads, 32 pts/thread: 32 x 32 x 16, natural-order scatter ----
__device__ __forceinline__ void fft16k_fwd(float2 (&v)[32], float2* __restrict__ sbuf, int tid)
{
    __syncthreads();   // prior sbuf readers done before pass-1 stores

    // ---- pass 1: DFT_32 over stride-512, twiddle W_N^{t*j} (pow-table ILP) ----
    fft32(v);
    {
        float sp, cp;
        sincospif((float)tid * (1.0f / 8192.0f), &sp, &cp);
        float2 s1 = make_float2(cp, -sp);
        float2 p[8];
        p[0] = make_float2(1.0f, 0.0f);
        p[1] = s1;
#pragma unroll
        for (int j = 2; j < 8; j++) p[j] = cmul(p[j - 1], s1);
        float2 b8  = cmul(p[7], s1);
        float2 b16 = cmul(b8, b8);
        float2 b24 = cmul(b16, b8);
#pragma unroll
        for (int j = 0; j < 32; j++) {
            int g = j >> 3, u = j & 7;
            float2 bg = (g == 1) ? b8 : ((g == 2) ? b16 : b24);
            float2 w = (g == 0) ? p[u] : ((u == 0) ? bg : cmul(bg, p[u]));
            sbuf[j * 512 + tid] = cmul(v[BR5(j)], w);
        }
    }
    __syncthreads();

    // ---- pass 2: within each 512-block, DFT_32 over stride-16, twiddle W_512^{m2*j2} ----
    {
        int j = tid >> 4, m2 = tid & 15;
        int base = j * 512 + m2;
#pragma unroll
        for (int r2 = 0; r2 < 32; r2++) v[r2] = sbuf[base + 16 * r2];
        __syncthreads();
        fft32(v);
        float sp, cp;
        sincospif((float)m2 * (1.0f / 256.0f), &sp, &cp);
        float2 s1 = make_float2(cp, -sp);
        float2 p[8];
        p[0] = make_float2(1.0f, 0.0f);
        p[1] = s1;
#pragma unroll
        for (int j2 = 2; j2 < 8; j2++) p[j2] = cmul(p[j2 - 1], s1);
        float2 b8  = cmul(p[7], s1);
        float2 b16 = cmul(b8, b8);
        float2 b24 = cmul(b16, b8);
        int pbase = j * 32;
#pragma unroll
        for (int j2 = 0; j2 < 32; j2++) {
            int g = j2 >> 3, u = j2 & 7;
            float2 bg = (g == 1) ? b8 : ((g == 2) ? b16 : b24);
            float2 w = (g == 0) ? p[u] : ((u == 0) ? bg : cmul(bg, p[u]));
            sbuf[(pbase + j2) * 16 + (m2 ^ (j2 & 15))] = cmul(v[BR5(j2)], w);
        }
    }
    __syncthreads();

    // ---- pass 3: two 16-pt FFTs per thread; scatter natural order (skewed) ----
#pragma unroll
    for (int c = 0; c < 2; c++) {
        int p = tid + c * 512;
        int sw = p & 15;
#pragma unroll
        for (int m2 = 0; m2 < 16; m2++) v[c * 16 + m2] = sbuf[p * 16 + (m2 ^ sw)];
    }
    __syncthreads();
    fft16(v);
    fft16(v + 16);
#pragma unroll
    for (int c = 0; c < 2; c++) {
        int p = tid + c * 512;
        int kb = (p >> 5) + 32 * (p & 31);
#pragma unroll
        for (int q = 0; q < 16; q++) {
            int k = kb + 1024 * BR4(q);
            sbuf[SKEW(k)] = v[c * 16 + q];
        }
    }
    __syncthreads();
}

// Hermitian unpack at arbitrary frequency j (mod N): returns (Xr, Xi, Tr, Ti)
__device__ __forceinline__ float4 unp(const float2* __restrict__ sbuf, int j) {
    int a = SKEW(j & (NFFT - 1));
    int c = SKEW((NFFT - j) & (NFFT - 1));
    float2 Z1 = sbuf[a], Z2 = sbuf[c];
    return make_float4(0.5f * (Z1.x + Z2.x),  0.5f * (Z1.y - Z2.y),
                       0.5f * (Z1.y + Z2.y), -0.5f * (Z1.x - Z2.x));
}

// Stencil + phase-only correlation at frequency k. pa/pt accumulate power-spectrum terms (f32).
__device__ __forceinline__ float2 phase_corr(const float2* __restrict__ sbuf, int k,
                                             float& pa, float& pt) {
    float4 U  = unp(sbuf, k);
    float xp = U.x * U.x + U.y * U.y;
    float tp = U.z * U.z + U.w * U.w;
    pa += fabsf(xp - tp);
    pt += tp;

    float4 Um = unp(sbuf, k - 1);
    float4 Up = unp(sbuf, k + 1);
    float Xwr = 0.5f * U.x - 0.25f * (Um.x + Up.x);
    float Xwi = 0.5f * U.y - 0.25f * (Um.y + Up.y);
    float Twr = 0.5f * U.z - 0.25f * (Um.z + Up.z);
    float Twi = 0.5f * U.w - 0.25f * (Um.w + Up.w);
    float Cr = Xwr * Twr + Xwi * Twi;   // Xw * conj(Tw)
    float Ci = Xwi * Twr - Xwr * Twi;
    float inv = rsqrtf(Cr * Cr + Ci * Ci);
    return make_float2(Cr * inv, Ci * inv);
}

// ---------------- main per-row kernel ----------------
__global__ void __launch_bounds__(NT, 1)
row_kernel(const float* __restrict__ pred, const float* __restrict__ targ,
           const int* __restrict__ ip, const int* __restrict__ ep,
           float* __restrict__ out)
{
    extern __shared__ char smem[];
    float2* sbuf = (float2*)smem;
    Scr* scr = (Scr*)(smem + (size_t)SBUF_N * sizeof(float2));

    const int tid  = threadIdx.x;
    const int lane = tid & 31;
    const int wid  = tid >> 5;
    const int b    = blockIdx.x;
    const int ii   = *ip;
    const float* x = pred + (size_t)ii * NB * NS + (size_t)b * NS;
    const float* y = targ + (size_t)b * NS;

    // ---- single global read of the row; feeds stats, MI, and FFT input ----
    float2 v[32];
#pragma unroll
    for (int r = 0; r < 32; r++) {
        int n = tid + 512 * r;
        v[r] = make_float2(x[n], y[n]);
    }

    // ================= Phase 1: Pearson stats + min/max (f32 partials) =================
    float sx = 0.f, sy = 0.f, sxy = 0.f, sxx = 0.f, syy = 0.f;
    float xmn = 3.4e38f, xmx = -3.4e38f, ymn = 3.4e38f, ymx = -3.4e38f;
#pragma unroll
    for (int r = 0; r < 32; r++) {
        float xv = v[r].x, yv = v[r].y;
        sx += xv; sy += yv;
        sxy = fmaf(xv, yv, sxy);
        sxx = fmaf(xv, xv, sxx);
        syy = fmaf(yv, yv, syy);
        xmn = fminf(xmn, xv); xmx = fmaxf(xmx, xv);
        ymn = fminf(ymn, yv); ymx = fmaxf(ymx, yv);
    }
#pragma unroll
    for (int o = 16; o; o >>= 1) {
        sx  += __shfl_down_sync(0xffffffffu, sx,  o);
        sy  += __shfl_down_sync(0xffffffffu, sy,  o);
        sxy += __shfl_down_sync(0xffffffffu, sxy, o);
        sxx += __shfl_down_sync(0xffffffffu, sxx, o);
        syy += __shfl_down_sync(0xffffffffu, syy, o);
        xmn = fminf(xmn, __shfl_down_sync(0xffffffffu, xmn, o));
        xmx = fmaxf(xmx, __shfl_down_sync(0xffffffffu, xmx, o));
        ymn = fminf(ymn, __shfl_down_sync(0xffffffffu, ymn, o));
        ymx = fmaxf(ymx, __shfl_down_sync(0xffffffffu, ymx, o));
    }
    if (lane == 0) {
        scr->red[0][wid] = (double)sx;  scr->red[1][wid] = (double)sy;
        scr->red[2][wid] = (double)sxy;
        scr->red[3][wid] = (double)sxx; scr->red[4][wid] = (double)syy;
        scr->fmm[0][wid] = xmn; scr->fmm[1][wid] = xmx;
        scr->fmm[2][wid] = ymn; scr->fmm[3][wid] = ymx;
    }
    if (tid < 100) scr->hist[tid] = 0;   // zero MI histogram concurrently
    __syncthreads();
    if (tid < 32) {
        bool a = (lane < 16);
        double r0 = a ? scr->red[0][lane] : 0.0;
        double r1 = a ? scr->red[1][lane] : 0.0;
        double r2 = a ? scr->red[2][lane] : 0.0;
        double r3 = a ? scr->red[3][lane] : 0.0;
        double r4 = a ? scr->red[4][lane] : 0.0;
        float m0 = a ? scr->fmm[0][lane] :  3.4e38f;
        float m1 = a ? scr->fmm[1][lane] : -3.4e38f;
        float m2 = a ? scr->fmm[2][lane] :  3.4e38f;
        float m3v = a ? scr->fmm[3][lane] : -3.4e38f;
#pragma unroll
        for (int o = 16; o; o >>= 1) {
            r0 += __shfl_down_sync(0xffffffffu, r0, o);
            r1 += __shfl_down_sync(0xffffffffu, r1, o);
            r2 += __shfl_down_sync(0xffffffffu, r2, o);
            r3 += __shfl_down_sync(0xffffffffu, r3, o);
            r4 += __shfl_down_sync(0xffffffffu, r4, o);
            m0 = fminf(m0, __shfl_down_sync(0xffffffffu, m0, o));
            m1 = fmaxf(m1, __shfl_down_sync(0xffffffffu, m1, o));
            m2 = fminf(m2, __shfl_down_sync(0xffffffffu, m2, o));
            m3v = fmaxf(m3v, __shfl_down_sync(0xffffffffu, m3v, o));
        }
        if (lane == 0) {
            const double N = (double)NS;
            double num = N * r2 - r0 * r1;
            double den = sqrt((N * r3 - r0 * r0) * (N * r4 - r1 * r1));
            atomicAdd(&g_acc[0], 1.0 - num / den);
            scr->bc[0] = m0; scr->bc[1] = m1; scr->bc[2] = m2; scr->bc[3] = m3v;
        }
    }
    __syncthreads();
    xmn = scr->bc[0]; xmx = scr->bc[1]; ymn = scr->bc[2]; ymx = scr->bc[3];

    // ================= Phase 2: mutual information (warp-dedup atomics) =================
    {
        float bwx = __fdiv_rn(xmx - xmn, 10.0f);
        float bwy = __fdiv_rn(ymx - ymn, 10.0f);
#pragma unroll
        for (int r = 0; r < 32; r++) {
            int ix = (int)__fdiv_rn(v[r].x - xmn, bwx);
            int iy = (int)__fdiv_rn(v[r].y - ymn, bwy);
            ix = min(max(ix, 0), 9);
            iy = min(max(iy, 0), 9);
            int code = ix * 10 + iy;
            unsigned mk = __match_any_sync(0xffffffffu, code);
            if (lane == (__ffs(mk) - 1)) atomicAdd(&scr->hist[code], __popc(mk));
        }
    }
    __syncthreads();
    if (tid < 32) {
        const float denom = 8388608.0f;  // B*S — faithful to reference normalization
        float rs = 0.f;
        if (lane < 10) {
#pragma unroll
            for (int c = 0; c < 10; c++) rs += (float)scr->hist[lane * 10 + c];
            scr->hxy[lane] = rs;
        } else if (lane < 20) {
            int c = lane - 10;
#pragma unroll
            for (int a = 0; a < 10; a++) rs += (float)scr->hist[a * 10 + c];
            scr->hxy[lane] = rs;
        }
        __syncwarp();
        float mi = 0.f;
#pragma unroll
        for (int u = 0; u < 4; u++) {
            int l = lane + 32 * u;
            if (l < 100) {
                int a2 = l / 10, c2 = l - 10 * a2;
                float px  = scr->hxy[a2] / denom;
                float py  = scr->hxy[10 + c2] / denom;
                float pxy = (float)scr->hist[l] / denom;
                mi += pxy * logf((pxy + 1e-8f) / (px * py + 1e-8f));
            }
        }
        float he = 0.f;
        if (lane < 20) {
            float p = scr->hxy[lane] / denom;
            he = -p * logf(p + 1e-8f);
        }
#pragma unroll
        for (int o = 16; o; o >>= 1) {
            mi += __shfl_down_sync(0xffffffffu, mi, o);
            he += __shfl_down_sync(0xffffffffu, he, o);
        }
        if (lane == 0) atomicAdd(&g_acc[2], (double)(mi / (he * 0.5f)));
    }

    // ================= Phase 3: single unwindowed FFT Z = FFT(x + i*y) =================
    fft16k_fwd(v, sbuf, tid);   // natural-order spectrum in sbuf (skewed)

    // ---- Phase A: power spectrum + freq-domain Hann stencil + phase-only C[k]
    float pa = 0.f, pt = 0.f;
#pragma unroll
    for (int r = 0; r < 16; r++) {
        v[r] = phase_corr(sbuf, tid + 512 * r, pa, pt);
    }
    float2 c81 = make_float2(0.f, 0.f);
    if (tid == 0) c81 = phase_corr(sbuf, HFFT, pa, pt);   // k=8192: Ci exactly 0
    __syncthreads();

    // ---- Phase B: store half-spectrum C[0..8192] at plain indices (no extension) ----
#pragma unroll
    for (int r = 0; r < 16; r++) {
        sbuf[tid + 512 * r] = v[r];
    }
    if (tid == 0) sbuf[HFFT] = c81;

    // power-spectrum reduction; its barrier also orders Phase B writes before prep reads
#pragma unroll
    for (int o = 16; o; o >>= 1) {
        pa += __shfl_down_sync(0xffffffffu, pa, o);
        pt += __shfl_down_sync(0xffffffffu, pt, o);
    }
    if (lane == 0) { scr->red[0][wid] = (double)pa; scr->red[1][wid] = (double)pt; }
    __syncthreads();
    if (tid < 32) {
        double p0 = (lane < 16) ? scr->red[0][lane] : 0.0;
        double p1 = (lane < 16) ? scr->red[1][lane] : 0.0;
#pragma unroll
        for (int o = 16; o; o >>= 1) {
            p0 += __shfl_down_sync(0xffffffffu, p0, o);
            p1 += __shfl_down_sync(0xffffffffu, p1, o);
        }
        if (lane == 0) {
            atomicAdd(&g_acc[3], p0);
            atomicAdd(&g_acc[4], p1);
        }
    }

    // ================= Phase 4: real inverse FFT as 8192-pt complex FFT =================
    // Zf[k] = E + i*cw*O, E=(C[k]+conj(C[8192-k]))/2, O=(C[k]-conj(C[8192-k]))/2,
    // cw = e^{+i pi k/8192}. Feed V = conj(Zf); forward FFT output m: Re=M*c[2m], -Im=M*c[2m+1].
    {
        float sp, cp;
        sincospif((float)tid * (1.0f / 8192.0f), &sp, &cp);  // base e^{+i pi tid/8192} = (cp, sp)
#pragma unroll
        for (int r = 0; r < 16; r++) {
            int k = tid + 512 * r;
            float2 C1 = sbuf[k];
            float2 C2 = sbuf[HFFT - k];
            float Er = 0.5f * (C1.x + C2.x), Ei = 0.5f * (C1.y - C2.y);
            float Or = 0.5f * (C1.x - C2.x), Oi = 0.5f * (C1.y + C2.y);
            // cw = base * e^{+i pi r/16}; e^{+i pi r/16} = (twc(r), -tws(r))
            float cwr = cp * twc(r) + sp * tws(r);
            float cwi = sp * twc(r) - cp * tws(r);
            float Zfr = Er - (cwr * Oi + cwi * Or);
            float Zfi = Ei + (cwr * Or - cwi * Oi);
            v[r] = make_float2(Zfr, -Zfi);     // conj(Zf)
        }
    }

    // ---- FFT#2 pass 1: DFT16 over r (stride 512), twiddle W_8192^{t*j1}, store [j1][t] ----
    fft16(v);
    {
        float sp, cp;
        sincospif((float)tid * (1.0f / 4096.0f), &sp, &cp);
        float2 s1 = make_float2(cp, -sp);
        float2 p[8];
        p[0] = make_float2(1.0f, 0.0f);
        p[1] = s1;
#pragma unroll
        for (int j = 2; j < 8; j++) p[j] = cmul(p[j - 1], s1);
        float2 b8 = cmul(p[7], s1);
#pragma unroll
        for (int j1 = 0; j1 < 16; j1++) {
            float2 w = (j1 < 8) ? p[j1] : ((j1 == 8) ? b8 : cmul(b8, p[j1 - 8]));
            sbuf[CB2 + j1 * 512 + tid] = cmul(v[BR4(j1)], w);
        }
    }
    __syncthreads();   // the ONLY barrier inside FFT#2 (passes 2-3 are warp-local)

    float bv = -3.4e38f; int bi = 0;
    {
        const int wrp = tid >> 5, l = tid & 31;
        const int rowb = CB2 + (wrp << 9);

        // ---- pass 2: row = warp; DFT16 over u (stride 32), twiddle W_512^{l*j2} ----
#pragma unroll
        for (int u = 0; u < 16; u++) v[u] = sbuf[rowb + l + 32 * u];
        fft16(v);
        {
            float sp, cp;
            sincospif((float)l * (1.0f / 256.0f), &sp, &cp);
            float2 s1 = make_float2(cp, -sp);
            float2 p[8];
            p[0] = make_float2(1.0f, 0.0f);
            p[1] = s1;
#pragma unroll
            for (int j = 2; j < 8; j++) p[j] = cmul(p[j - 1], s1);
            float2 b8 = cmul(p[7], s1);
#pragma unroll
            for (int j2 = 0; j2 < 16; j2++) {
                float2 w = (j2 < 8) ? p[j2] : ((j2 == 8) ? b8 : cmul(b8, p[j2 - 8]));
                sbuf[rowb + j2 * 32 + (l ^ (2 * j2))] = cmul(v[BR4(j2)], w);
            }
        }
        __syncwarp();

        // ---- pass 3: 32-blocks, pair of lanes; DFT16 over u3 + W_32^{j3} + shuffle radix-2 ----
        const int j2 = (tid >> 1) & 15;
        const int m3 = tid & 1;
        const int base3 = rowb + (j2 << 5);
        const int sw = 2 * j2;
#pragma unroll
        for (int u = 0; u < 16; u++) v[u] = sbuf[base3 + ((m3 + 2 * u) ^ sw)];
        fft16(v);
        if (m3) {
#pragma unroll
            for (int q = 0; q < 16; q++) {
                int j3 = BR4(q);
                v[q] = cmul(v[q], make_float2(twc(j3), tws(j3)));
            }
        }
        const int kb = wrp + (j2 << 4) + (m3 << 12);   // j1 + 16*j2 + 4096*s4
#pragma unroll
        for (int q = 0; q < 16; q++) {
            float px = __shfl_xor_sync(0xffffffffu, v[q].x, 1);
            float py = __shfl_xor_sync(0xffffffffu, v[q].y, 1);
            float ox, oy;
            if (m3 == 0) { ox = v[q].x + px; oy = v[q].y + py; }   // Y0 + W*Y1
            else         { ox = px - v[q].x; oy = py - v[q].y; }   // Y0 - W*Y1
            int n0 = (kb + (BR4(q) << 8)) << 1;   // time index 2*kappa
            float e0 = ox;    // M * c[2k]
            float e1 = -oy;   // M * c[2k+1]
            if (e0 > bv || (e0 == bv && n0 < bi)) { bv = e0; bi = n0; }
            if (e1 > bv || (e1 == bv && n0 + 1 < bi)) { bv = e1; bi = n0 + 1; }
        }
    }

    // block argmax (value, min index)
    for (int o = 16; o; o >>= 1) {
        float ov = __shfl_down_sync(0xffffffffu, bv, o);
        int   oi = __shfl_down_sync(0xffffffffu, bi, o);
        if (ov > bv || (ov == bv && oi < bi)) { bv = ov; bi = oi; }
    }
    if (lane == 0) { scr->amaxv[wid] = bv; scr->amaxi[wid] = bi; }
    __syncthreads();
    if (tid < 32) {
        bool a = (lane < 16);
        float ov = a ? scr->amaxv[lane] : -3.4e38f;
        int   oi = a ? scr->amaxi[lane] : 0x7fffffff;
#pragma unroll
        for (int o = 16; o; o >>= 1) {
            float pv = __shfl_down_sync(0xffffffffu, ov, o);
            int   pi = __shfl_down_sync(0xffffffffu, oi, o);
            if (pv > ov || (pv == ov && pi < oi)) { ov = pv; oi = pi; }
        }
        if (lane == 0)
            atomicAdd(&g_acc[1], (double)cospif((float)oi * (1.0f / 8192.0f)));
    }

    // ================= Finalize: last block computes the loss and resets state =================
    if (tid == 0) {
        __threadfence();
        unsigned t = atomicAdd(&g_cnt, 1u);
        scr->last = (t == (unsigned)(NB - 1));
    }
    __syncthreads();
    if (scr->last && tid == 0) {
        __threadfence();
        double a0 = atomicAdd(&g_acc[0], 0.0);
        double a1 = atomicAdd(&g_acc[1], 0.0);
        double a2 = atomicAdd(&g_acc[2], 0.0);
        double a3 = atomicAdd(&g_acc[3], 0.0);
        double a4 = atomicAdd(&g_acc[4], 0.0);
        int e = *ep;
        double loss = a0 / (double)NB;
        if (e >= 400) {
            loss += 1.0 - a1 / (double)NB;   // phase correlation term
            loss += a3 / a4;                 // power spectrum (means over same count cancel)
        }
        if (e >= 700) {
            loss += 1.0 - a2 / (double)NB;   // mutual information term
        }
        out[0] = (float)loss;
        // reset accumulators for the next (graph-replayed) launch
        g_acc[0] = 0.0; g_acc[1] = 0.0; g_acc[2] = 0.0; g_acc[3] = 0.0; g_acc[4] = 0.0;
        __threadfence();
        g_cnt = 0u;
    }
}

extern "C" void kernel_launch(void* const* d_in, const int* in_sizes, int n_in,
                              void* d_out, int out_size) {
    const float* pred = (const float*)d_in[0];
    const float* targ = (const float*)d_in[1];
    const int*   ip   = (const int*)d_in[2];
    const int*   ep   = (const int*)d_in[3];
    float* out = (float*)d_out;

    size_t smem = (size_t)SBUF_N * sizeof(float2) + sizeof(Scr);
    cudaFuncSetAttribute(row_kernel, cudaFuncAttributeMaxDynamicSharedMemorySize, (int)smem);

    row_kernel<<<NB, NT, smem>>>(pred, targ, ip, ep, out);
}

// round 12
// speedup vs baseline: 2.5196x; 1.6543x over previous
#include <cuda_runtime.h>

#define NB 512
#define NS 16384
#define NFFT 16384
#define HFFT 8192
#define NT 512
#define SBUF_N 16896
#define SKEW(k) ((k) + ((k) >> 5))
#define CB2 8448   // FFT#2 staging base (slots 8448..16639; C lives in 0..8192)

typedef unsigned long long u64;

// Global accumulators: 0=pearson(1-r) sum, 1=cos sum, 2=nmi sum, 3=|xp-tp| sum, 4=tp sum
__device__ double g_acc[5];
__device__ unsigned g_cnt;

struct Scr {
    double red[5][16];
    float  fmm[4][16];
    float  hxy[20];
    int    hist[100];
    float  amaxv[16];
    int    amaxi[16];
    float  bc[4];
    int    last;
};

// ---------------- packed f32x2 helpers (sm_103a FFMA2 path) ----------------
__device__ __forceinline__ u64 PKF(float a, float b) {
    u64 r;
    asm("mov.b64 %0, {%1, %2};" : "=l"(r) : "r"(__float_as_uint(a)), "r"(__float_as_uint(b)));
    return r;
}
__device__ __forceinline__ void UNPK(u64 a, float& x, float& y) {
    unsigned lo, hi;
    asm("mov.b64 {%0, %1}, %2;" : "=r"(lo), "=r"(hi) : "l"(a));
    x = __uint_as_float(lo); y = __uint_as_float(hi);
}
__device__ __forceinline__ u64 ADD2(u64 a, u64 b) {
    u64 r; asm("add.rn.f32x2 %0, %1, %2;" : "=l"(r) : "l"(a), "l"(b)); return r;
}
__device__ __forceinline__ u64 MUL2(u64 a, u64 b) {
    u64 r; asm("mul.rn.f32x2 %0, %1, %2;" : "=l"(r) : "l"(a), "l"(b)); return r;
}
__device__ __forceinline__ u64 FMA2(u64 a, u64 b, u64 c) {
    u64 r; asm("fma.rn.f32x2 %0, %1, %2, %3;" : "=l"(r) : "l"(a), "l"(b), "l"(c)); return r;
}
__device__ __forceinline__ u64 SWP(u64 a) {
    u64 r;
    asm("{\n\t.reg .b32 lo, hi;\n\tmov.b64 {lo, hi}, %1;\n\tmov.b64 %0, {hi, lo};\n\t}"
        : "=l"(r) : "l"(a));
    return r;
}
__device__ __forceinline__ u64 SUB2(u64 a, u64 b) {   // a - b
    return FMA2(b, PKF(-1.0f, -1.0f), a);
}

// ---------------- small helpers ----------------
__device__ __forceinline__ float2 cmul(float2 a, float2 b) {
    return make_float2(a.x * b.x - a.y * b.y, a.x * b.y + a.y * b.x);
}

__device__ __forceinline__ int BR5(int x) {
    return ((x & 1) << 4) | ((x & 2) << 2) | (x & 4) | ((x & 8) >> 2) | ((x & 16) >> 4);
}
__device__ __forceinline__ int BR4(int x) {
    return ((x & 1) << 3) | ((x & 2) << 1) | ((x & 4) >> 1) | ((x & 8) >> 3);
}

// twiddle constants exp(-i*pi*e/16); switch form folds to immediates under full unroll
__device__ __forceinline__ float twc(int e) {
    switch (e & 15) {
        case 0:  return  1.0f;
        case 1:  return  0.980785280403f;
        case 2:  return  0.923879532511f;
        case 3:  return  0.831469612303f;
        case 4:  return  0.707106781187f;
        case 5:  return  0.555570233020f;
        case 6:  return  0.382683432365f;
        case 7:  return  0.195090322016f;
        case 8:  return  0.0f;
        case 9:  return -0.195090322016f;
        case 10: return -0.382683432365f;
        case 11: return -0.555570233020f;
        case 12: return -0.707106781187f;
        case 13: return -0.831469612303f;
        case 14: return -0.923879532511f;
        default: return -0.980785280403f;
    }
}
__device__ __forceinline__ float tws(int e) {
    switch (e & 15) {
        case 0:  return  0.0f;
        case 1:  return -0.195090322016f;
        case 2:  return -0.382683432365f;
        case 3:  return -0.555570233020f;
        case 4:  return -0.707106781187f;
        case 5:  return -0.831469612303f;
        case 6:  return -0.923879532511f;
        case 7:  return -0.980785280403f;
        case 8:  return -1.0f;
        case 9:  return -0.980785280403f;
        case 10: return -0.923879532511f;
        case 11: return -0.831469612303f;
        case 12: return -0.707106781187f;
        case 13: return -0.555570233020f;
        case 14: return -0.382683432365f;
        default: return -0.195090322016f;
    }
}

// Packed butterfly: p,q <- p+q, (p-q)*W(e), e compile-time after unroll.
__device__ __forceinline__ void bflyp(u64& p, u64& q, int e) {
    u64 s = ADD2(p, q);
    u64 d = SUB2(p, q);
    p = s;
    e &= 15;
    if (e == 0) {
        q = d;
    } else if (e == 8) {
        q = MUL2(SWP(d), PKF(1.0f, -1.0f));   // (dy, -dx)
    } else {
        q = FMA2(SWP(d), PKF(-tws(e), tws(e)), MUL2(d, PKF(twc(e), twc(e))));
    }
}

// Packed cmul by compile-time-constant twiddle (c, s)
__device__ __forceinline__ u64 cmulc(u64 a, float c, float s) {
    return FMA2(SWP(a), PKF(-s, s), MUL2(a, PKF(c, c)));
}

// Packed-data cmul by runtime float2 w (scalar core: packed setup is break-even)
__device__ __forceinline__ u64 cmulw(u64 a, float2 w) {
    float ax, ay; UNPK(a, ax, ay);
    return PKF(fmaf(ax, w.x, -ay * w.y), fmaf(ax, w.y, ay * w.x));
}

// DIF radix-2 FFT of 32 packed points. Output position q holds frequency brev5(q).
__device__ __forceinline__ void fft32(u64* v) {
#pragma unroll
    for (int h = 16; h >= 1; h >>= 1) {
#pragma unroll
        for (int g = 0; g < 32; g += 2 * h) {
#pragma unroll
            for (int j = 0; j < h; j++) {
                bflyp(v[g + j], v[g + j + h], j * (16 / h));
            }
        }
    }
}

// DIF radix-2 FFT of 16 packed points. Output position q holds frequency brev4(q).
__device__ __forceinline__ void fft16(u64* v) {
#pragma unroll
    for (int h = 8; h >= 1; h >>= 1) {
#pragma unroll
        for (int g = 0; g < 16; g += 2 * h) {
#pragma unroll
            for (int j = 0; j < h; j++) {
                bflyp(v[g + j], v[g + j + h], j * (16 / h));
            }
        }
    }
}

// ---- FFT#1: 16384-pt, 512 threads, 32 pts/thread: 32 x 32 x 16, natural-order scatter ----
__device__ __forceinline__ void fft16k_fwd(u64 (&v)[32], u64* __restrict__ sbuf, int tid)
{
    __syncthreads();   // prior sbuf readers done before pass-1 stores

    // ---- pass 1: DFT_32 over stride-512, twiddle W_N^{t*j} (pow-table ILP) ----
    fft32(v);
    {
        float sp, cp;
        sincospif((float)tid * (1.0f / 8192.0f), &sp, &cp);
        float2 s1 = make_float2(cp, -sp);
        float2 p[8];
        p[0] = make_float2(1.0f, 0.0f);
        p[1] = s1;
#pragma unroll
        for (int j = 2; j < 8; j++) p[j] = cmul(p[j - 1], s1);
        float2 b8  = cmul(p[7], s1);
        float2 b16 = cmul(b8, b8);
        float2 b24 = cmul(b16, b8);
#pragma unroll
        for (int j = 0; j < 32; j++) {
            int g = j >> 3, u = j & 7;
            float2 bg = (g == 1) ? b8 : ((g == 2) ? b16 : b24);
            float2 w = (g == 0) ? p[u] : ((u == 0) ? bg : cmul(bg, p[u]));
            sbuf[j * 512 + tid] = cmulw(v[BR5(j)], w);
        }
    }
    __syncthreads();

    // ---- pass 2: within each 512-block, DFT_32 over stride-16, twiddle W_512^{m2*j2} ----
    // Row j is touched ONLY by its own half-warp (threads 16j..16j+15) -> warp-level sync.
    {
        int j = tid >> 4, m2 = tid & 15;
        int base = j * 512 + m2;
#pragma unroll
        for (int r2 = 0; r2 < 32; r2++) v[r2] = sbuf[base + 16 * r2];
        __syncwarp();
        fft32(v);
        float sp, cp;
        sincospif((float)m2 * (1.0f / 256.0f), &sp, &cp);
        float2 s1 = make_float2(cp, -sp);
        float2 p[8];
        p[0] = make_float2(1.0f, 0.0f);
        p[1] = s1;
#pragma unroll
        for (int j2 = 2; j2 < 8; j2++) p[j2] = cmul(p[j2 - 1], s1);
        float2 b8  = cmul(p[7], s1);
        float2 b16 = cmul(b8, b8);
        float2 b24 = cmul(b16, b8);
        int pbase = j * 32;
#pragma unroll
        for (int j2 = 0; j2 < 32; j2++) {
            int g = j2 >> 3, u = j2 & 7;
            float2 bg = (g == 1) ? b8 : ((g == 2) ? b16 : b24);
            float2 w = (g == 0) ? p[u] : ((u == 0) ? bg : cmul(bg, p[u]));
            sbuf[(pbase + j2) * 16 + (m2 ^ (j2 & 15))] = cmulw(v[BR5(j2)], w);
        }
    }
    __syncthreads();

    // ---- pass 3: two 16-pt FFTs per thread; scatter natural order (skewed) ----
#pragma unroll
    for (int c = 0; c < 2; c++) {
        int p = tid + c * 512;
        int sw = p & 15;
#pragma unroll
        for (int m2 = 0; m2 < 16; m2++) v[c * 16 + m2] = sbuf[p * 16 + (m2 ^ sw)];
    }
    __syncthreads();
    fft16(v);
    fft16(v + 16);
#pragma unroll
    for (int c = 0; c < 2; c++) {
        int p = tid + c * 512;
        int kb = (p >> 5) + 32 * (p & 31);
#pragma unroll
        for (int q = 0; q < 16; q++) {
            int k = kb + 1024 * BR4(q);
            sbuf[SKEW(k)] = v[c * 16 + q];
        }
    }
    __syncthreads();
}

// Hermitian unpack at arbitrary frequency j (mod N): returns (Xr, Xi, Tr, Ti)
__device__ __forceinline__ float4 unp(const float2* __restrict__ sbuf, int j) {
    int a = SKEW(j & (NFFT - 1));
    int c = SKEW((NFFT - j) & (NFFT - 1));
    float2 Z1 = sbuf[a], Z2 = sbuf[c];
    return make_float4(0.5f * (Z1.x + Z2.x),  0.5f * (Z1.y - Z2.y),
                       0.5f * (Z1.y + Z2.y), -0.5f * (Z1.x - Z2.x));
}

// Stencil + phase-only correlation at frequency k. pa/pt accumulate power-spectrum terms (f32).
__device__ __forceinline__ float2 phase_corr(const float2* __restrict__ sbuf, int k,
                                             float& pa, float& pt) {
    float4 U  = unp(sbuf, k);
    float xp = U.x * U.x + U.y * U.y;
    float tp = U.z * U.z + U.w * U.w;
    pa += fabsf(xp - tp);
    pt += tp;

    float4 Um = unp(sbuf, k - 1);
    float4 Up = unp(sbuf, k + 1);
    float Xwr = 0.5f * U.x - 0.25f * (Um.x + Up.x);
    float Xwi = 0.5f * U.y - 0.25f * (Um.y + Up.y);
    float Twr = 0.5f * U.z - 0.25f * (Um.z + Up.z);
    float Twi = 0.5f * U.w - 0.25f * (Um.w + Up.w);
    float Cr = Xwr * Twr + Xwi * Twi;   // Xw * conj(Tw)
    float Ci = Xwi * Twr - Xwr * Twi;
    float inv = rsqrtf(Cr * Cr + Ci * Ci);
    return make_float2(Cr * inv, Ci * inv);
}

// ---------------- main per-row kernel ----------------
__global__ void __launch_bounds__(NT, 1)
row_kernel(const float* __restrict__ pred, const float* __restrict__ targ,
           const int* __restrict__ ip, const int* __restrict__ ep,
           float* __restrict__ out)
{
    extern __shared__ char smem[];
    u64*    sbufP = (u64*)smem;
    float2* sbufF = (float2*)smem;
    Scr* scr = (Scr*)(smem + (size_t)SBUF_N * sizeof(float2));

    const int tid  = threadIdx.x;
    const int lane = tid & 31;
    const int wid  = tid >> 5;
    const int b    = blockIdx.x;
    const int ii   = *ip;
    const float* x = pred + (size_t)ii * NB * NS + (size_t)b * NS;
    const float* y = targ + (size_t)b * NS;

    // ---- single global read of the row; stats fused with load; packed store ----
    u64 v[32];
    float sx = 0.f, sy = 0.f, sxy = 0.f, sxx = 0.f, syy = 0.f;
    float xmn = 3.4e38f, xmx = -3.4e38f, ymn = 3.4e38f, ymx = -3.4e38f;
#pragma unroll
    for (int r = 0; r < 32; r++) {
        int n = tid + 512 * r;
        float xv = x[n], yv = y[n];
        sx += xv; sy += yv;
        sxy = fmaf(xv, yv, sxy);
        sxx = fmaf(xv, xv, sxx);
        syy = fmaf(yv, yv, syy);
        xmn = fminf(xmn, xv); xmx = fmaxf(xmx, xv);
        ymn = fminf(ymn, yv); ymx = fmaxf(ymx, yv);
        v[r] = PKF(xv, yv);
    }
#pragma unroll
    for (int o = 16; o; o >>= 1) {
        sx  += __shfl_down_sync(0xffffffffu, sx,  o);
        sy  += __shfl_down_sync(0xffffffffu, sy,  o);
        sxy += __shfl_down_sync(0xffffffffu, sxy, o);
        sxx += __shfl_down_sync(0xffffffffu, sxx, o);
        syy += __shfl_down_sync(0xffffffffu, syy, o);
        xmn = fminf(xmn, __shfl_down_sync(0xffffffffu, xmn, o));
        xmx = fmaxf(xmx, __shfl_down_sync(0xffffffffu, xmx, o));
        ymn = fminf(ymn, __shfl_down_sync(0xffffffffu, ymn, o));
        ymx = fmaxf(ymx, __shfl_down_sync(0xffffffffu, ymx, o));
    }
    if (lane == 0) {
        scr->red[0][wid] = (double)sx;  scr->red[1][wid] = (double)sy;
        scr->red[2][wid] = (double)sxy;
        scr->red[3][wid] = (double)sxx; scr->red[4][wid] = (double)syy;
        scr->fmm[0][wid] = xmn; scr->fmm[1][wid] = xmx;
        scr->fmm[2][wid] = ymn; scr->fmm[3][wid] = ymx;
    }
    if (tid < 100) scr->hist[tid] = 0;   // zero MI histogram concurrently
    __syncthreads();
    if (tid < 32) {
        bool a = (lane < 16);
        double r0 = a ? scr->red[0][lane] : 0.0;
        double r1 = a ? scr->red[1][lane] : 0.0;
        double r2 = a ? scr->red[2][lane] : 0.0;
        double r3 = a ? scr->red[3][lane] : 0.0;
        double r4 = a ? scr->red[4][lane] : 0.0;
        float m0 = a ? scr->fmm[0][lane] :  3.4e38f;
        float m1 = a ? scr->fmm[1][lane] : -3.4e38f;
        float m2 = a ? scr->fmm[2][lane] :  3.4e38f;
        float m3v = a ? scr->fmm[3][lane] : -3.4e38f;
#pragma unroll
        for (int o = 16; o; o >>= 1) {
            r0 += __shfl_down_sync(0xffffffffu, r0, o);
            r1 += __shfl_down_sync(0xffffffffu, r1, o);
            r2 += __shfl_down_sync(0xffffffffu, r2, o);
            r3 += __shfl_down_sync(0xffffffffu, r3, o);
            r4 += __shfl_down_sync(0xffffffffu, r4, o);
            m0 = fminf(m0, __shfl_down_sync(0xffffffffu, m0, o));
            m1 = fmaxf(m1, __shfl_down_sync(0xffffffffu, m1, o));
            m2 = fminf(m2, __shfl_down_sync(0xffffffffu, m2, o));
            m3v = fmaxf(m3v, __shfl_down_sync(0xffffffffu, m3v, o));
        }
        if (lane == 0) {
            const double N = (double)NS;
            double num = N * r2 - r0 * r1;
            double den = sqrt((N * r3 - r0 * r0) * (N * r4 - r1 * r1));
            atomicAdd(&g_acc[0], 1.0 - num / den);
            scr->bc[0] = m0; scr->bc[1] = m1; scr->bc[2] = m2; scr->bc[3] = m3v;
        }
    }
    __syncthreads();
    xmn = scr->bc[0]; xmx = scr->bc[1]; ymn = scr->bc[2]; ymx = scr->bc[3];

    // ================= Phase 2: mutual information (warp-dedup atomics) =================
    {
        float bwx = __fdiv_rn(xmx - xmn, 10.0f);
        float bwy = __fdiv_rn(ymx - ymn, 10.0f);
#pragma unroll
        for (int r = 0; r < 32; r++) {
            float xv, yv; UNPK(v[r], xv, yv);
            int ix = (int)__fdiv_rn(xv - xmn, bwx);
            int iy = (int)__fdiv_rn(yv - ymn, bwy);
            ix = min(max(ix, 0), 9);
            iy = min(max(iy, 0), 9);
            int code = ix * 10 + iy;
            unsigned mk = __match_any_sync(0xffffffffu, code);
            if (lane == (__ffs(mk) - 1)) atomicAdd(&scr->hist[code], __popc(mk));
        }
    }
    __syncthreads();
    if (tid < 32) {
        const float denom = 8388608.0f;  // B*S — faithful to reference normalization
        float rs = 0.f;
        if (lane < 10) {
#pragma unroll
            for (int c = 0; c < 10; c++) rs += (float)scr->hist[lane * 10 + c];
            scr->hxy[lane] = rs;
        } else if (lane < 20) {
            int c = lane - 10;
#pragma unroll
            for (int a = 0; a < 10; a++) rs += (float)scr->hist[a * 10 + c];
            scr->hxy[lane] = rs;
        }
        __syncwarp();
        float mi = 0.f;
#pragma unroll
        for (int u = 0; u < 4; u++) {
            int l = lane + 32 * u;
            if (l < 100) {
                int a2 = l / 10, c2 = l - 10 * a2;
                float px  = scr->hxy[a2] / denom;
                float py  = scr->hxy[10 + c2] / denom;
                float pxy = (float)scr->hist[l] / denom;
                mi += pxy * logf((pxy + 1e-8f) / (px * py + 1e-8f));
            }
        }
        float he = 0.f;
        if (lane < 20) {
            float p = scr->hxy[lane] / denom;
            he = -p * logf(p + 1e-8f);
        }
#pragma unroll
        for (int o = 16; o; o >>= 1) {
            mi += __shfl_down_sync(0xffffffffu, mi, o);
            he += __shfl_down_sync(0xffffffffu, he, o);
        }
        if (lane == 0) atomicAdd(&g_acc[2], (double)(mi / (he * 0.5f)));
    }

    // ================= Phase 3: single unwindowed FFT Z = FFT(x + i*y) =================
    fft16k_fwd(v, sbufP, tid);   // natural-order spectrum in sbuf (skewed)

    // ---- Phase A: power spectrum + freq-domain Hann stencil + phase-only C[k]
    float pa = 0.f, pt = 0.f;
#pragma unroll
    for (int r = 0; r < 16; r++) {
        float2 C = phase_corr(sbufF, tid + 512 * r, pa, pt);
        v[r] = PKF(C.x, C.y);
    }
    u64 c81 = 0;
    if (tid == 0) {
        float2 C = phase_corr(sbufF, HFFT, pa, pt);   // k=8192: Ci exactly 0
        c81 = PKF(C.x, C.y);
    }
    __syncthreads();

    // ---- Phase B: store half-spectrum C[0..8192] at plain indices (no extension) ----
#pragma unroll
    for (int r = 0; r < 16; r++) {
        sbufP[tid + 512 * r] = v[r];
    }
    if (tid == 0) sbufP[HFFT] = c81;

    // power-spectrum reduction; its barrier also orders Phase B writes before prep reads
#pragma unroll
    for (int o = 16; o; o >>= 1) {
        pa += __shfl_down_sync(0xffffffffu, pa, o);
        pt += __shfl_down_sync(0xffffffffu, pt, o);
    }
    if (lane == 0) { scr->red[0][wid] = (double)pa; scr->red[1][wid] = (double)pt; }
    __syncthreads();
    if (tid < 32) {
        double p0 = (lane < 16) ? scr->red[0][lane] : 0.0;
        double p1 = (lane < 16) ? scr->red[1][lane] : 0.0;
#pragma unroll
        for (int o = 16; o; o >>= 1) {
            p0 += __shfl_down_sync(0xffffffffu, p0, o);
            p1 += __shfl_down_sync(0xffffffffu, p1, o);
        }
        if (lane == 0) {
            atomicAdd(&g_acc[3], p0);
            atomicAdd(&g_acc[4], p1);
        }
    }

    // ================= Phase 4: real inverse FFT as 8192-pt complex FFT =================
    // Zf[k] = E + i*cw*O, E=(C[k]+conj(C[8192-k]))/2, O=(C[k]-conj(C[8192-k]))/2,
    // cw = e^{+i pi k/8192}. Feed V = conj(Zf); forward FFT output m: Re=M*c[2m], -Im=M*c[2m+1].
    {
        float sp, cp;
        sincospif((float)tid * (1.0f / 8192.0f), &sp, &cp);  // base e^{+i pi tid/8192} = (cp, sp)
#pragma unroll
        for (int r = 0; r < 16; r++) {
            int k = tid + 512 * r;
            float2 C1 = sbufF[k];
            float2 C2 = sbufF[HFFT - k];
            float Er = 0.5f * (C1.x + C2.x), Ei = 0.5f * (C1.y - C2.y);
            float Or = 0.5f * (C1.x - C2.x), Oi = 0.5f * (C1.y + C2.y);
            // cw = base * e^{+i pi r/16}; e^{+i pi r/16} = (twc(r), -tws(r))
            float cwr = cp * twc(r) + sp * tws(r);
            float cwi = sp * twc(r) - cp * tws(r);
            float Zfr = Er - (cwr * Oi + cwi * Or);
            float Zfi = Ei + (cwr * Or - cwi * Oi);
            v[r] = PKF(Zfr, -Zfi);     // conj(Zf)
        }
    }

    // ---- FFT#2 pass 1: DFT16 over r (stride 512), twiddle W_8192^{t*j1}, store [j1][t] ----
    fft16(v);
    {
        float sp, cp;
        sincospif((float)tid * (1.0f / 4096.0f), &sp, &cp);
        float2 s1 = make_float2(cp, -sp);
        float2 p[8];
        p[0] = make_float2(1.0f, 0.0f);
        p[1] = s1;
#pragma unroll
        for (int j = 2; j < 8; j++) p[j] = cmul(p[j - 1], s1);
        float2 b8 = cmul(p[7], s1);
#pragma unroll
        for (int j1 = 0; j1 < 16; j1++) {
            float2 w = (j1 < 8) ? p[j1] : ((j1 == 8) ? b8 : cmul(b8, p[j1 - 8]));
            sbufP[CB2 + j1 * 512 + tid] = cmulw(v[BR4(j1)], w);
        }
    }
    __syncthreads();   // the ONLY barrier inside FFT#2 (passes 2-3 are warp-local)

    float bv = -3.4e38f; int bi = 0;
    {
        const int wrp = tid >> 5, l = tid & 31;
        const int rowb = CB2 + (wrp << 9);

        // ---- pass 2: row = warp; DFT16 over u (stride 32), twiddle W_512^{l*j2} ----
#pragma unroll
        for (int u = 0; u < 16; u++) v[u] = sbufP[rowb + l + 32 * u];
        fft16(v);
        {
            float sp, cp;
            sincospif((float)l * (1.0f / 256.0f), &sp, &cp);
            float2 s1 = make_float2(cp, -sp);
            float2 p[8];
            p[0] = make_float2(1.0f, 0.0f);
            p[1] = s1;
#pragma unroll
            for (int j = 2; j < 8; j++) p[j] = cmul(p[j - 1], s1);
            float2 b8 = cmul(p[7], s1);
#pragma unroll
            for (int j2 = 0; j2 < 16; j2++) {
                float2 w = (j2 < 8) ? p[j2] : ((j2 == 8) ? b8 : cmul(b8, p[j2 - 8]));
                sbufP[rowb + j2 * 32 + (l ^ (2 * j2))] = cmulw(v[BR4(j2)], w);
            }
        }
        __syncwarp();

        // ---- pass 3: 32-blocks, pair of lanes; DFT16 over u3 + W_32^{j3} + shuffle radix-2 ----
        const int j2 = (tid >> 1) & 15;
        const int m3 = tid & 1;
        const int base3 = rowb + (j2 << 5);
        const int sw = 2 * j2;
#pragma unroll
        for (int u = 0; u < 16; u++) v[u] = sbufP[base3 + ((m3 + 2 * u) ^ sw)];
        fft16(v);
        if (m3) {
#pragma unroll
            for (int q = 0; q < 16; q++) {
                int j3 = BR4(q);
                v[q] = cmulc(v[q], twc(j3), tws(j3));
            }
        }
        const int kb = wrp + (j2 << 4) + (m3 << 12);   // j1 + 16*j2 + 4096*s4
#pragma unroll
        for (int q = 0; q < 16; q++) {
            float vx, vy; UNPK(v[q], vx, vy);
            float px = __shfl_xor_sync(0xffffffffu, vx, 1);
            float py = __shfl_xor_sync(0xffffffffu, vy, 1);
            float ox, oy;
            if (m3 == 0) { ox = vx + px; oy = vy + py; }   // Y0 + W*Y1
            else         { ox = px - vx; oy = py - vy; }   // Y0 - W*Y1
            int n0 = (kb + (BR4(q) << 8)) << 1;   // time index 2*kappa
            float e0 = ox;    // M * c[2k]
            float e1 = -oy;   // M * c[2k+1]
            if (e0 > bv || (e0 == bv && n0 < bi)) { bv = e0; bi = n0; }
            if (e1 > bv || (e1 == bv && n0 + 1 < bi)) { bv = e1; bi = n0 + 1; }
        }
    }

    // block argmax (value, min index)
    for (int o = 16; o; o >>= 1) {
        float ov = __shfl_down_sync(0xffffffffu, bv, o);
        int   oi = __shfl_down_sync(0xffffffffu, bi, o);
        if (ov > bv || (ov == bv && oi < bi)) { bv = ov; bi = oi; }
    }
    if (lane == 0) { scr->amaxv[wid] = bv; scr->amaxi[wid] = bi; }
    __syncthreads();
    if (tid < 32) {
        bool a = (lane < 16);
        float ov = a ? scr->amaxv[lane] : -3.4e38f;
        int   oi = a ? scr->amaxi[lane] : 0x7fffffff;
#pragma unroll
        for (int o = 16; o; o >>= 1) {
            float pv = __shfl_down_sync(0xffffffffu, ov, o);
            int   pi = __shfl_down_sync(0xffffffffu, oi, o);
            if (pv > ov || (pv == ov && pi < oi)) { ov = pv; oi = pi; }
        }
        if (lane == 0)
            atomicAdd(&g_acc[1], (double)cospif((float)oi * (1.0f / 8192.0f)));
    }

    // ================= Finalize: last block computes the loss and resets state =================
    if (tid == 0) {
        __threadfence();
        unsigned t = atomicAdd(&g_cnt, 1u);
        scr->last = (t == (unsigned)(NB - 1));
    }
    __syncthreads();
    if (scr->last && tid == 0) {
        __threadfence();
        double a0 = atomicAdd(&g_acc[0], 0.0);
        double a1 = atomicAdd(&g_acc[1], 0.0);
        double a2 = atomicAdd(&g_acc[2], 0.0);
        double a3 = atomicAdd(&g_acc[3], 0.0);
        double a4 = atomicAdd(&g_acc[4], 0.0);
        int e = *ep;
        double loss = a0 / (double)NB;
        if (e >= 400) {
            loss += 1.0 - a1 / (double)NB;   // phase correlation term
            loss += a3 / a4;                 // power spectrum (means over same count cancel)
        }
        if (e >= 700) {
            loss += 1.0 - a2 / (double)NB;   // mutual information term
        }
        out[0] = (float)loss;
        // reset accumulators for the next (graph-replayed) launch
        g_acc[0] = 0.0; g_acc[1] = 0.0; g_acc[2] = 0.0; g_acc[3] = 0.0; g_acc[4] = 0.0;
        __threadfence();
        g_cnt = 0u;
    }
}

extern "C" void kernel_launch(void* const* d_in, const int* in_sizes, int n_in,
                              void* d_out, int out_size) {
    const float* pred = (const float*)d_in[0];
    const float* targ = (const float*)d_in[1];
    const int*   ip   = (const int*)d_in[2];
    const int*   ep   = (const int*)d_in[3];
    float* out = (float*)d_out;

    size_t smem = (size_t)SBUF_N * sizeof(float2) + sizeof(Scr);
    cudaFuncSetAttribute(row_kernel, cudaFuncAttributeMaxDynamicSharedMemorySize, (int)smem);

    row_kernel<<<NB, NT, smem>>>(pred, targ, ip, ep, out);
}